// round 11
// baseline (speedup 1.0000x reference)
#include <cuda_runtime.h>
#include <cuda_fp16.h>
#include <cstdint>
#include <cstddef>

// ---------------------------------------------------------------------------
// out[8192,4096] = x[8192,4096] @ W^T + b,  W = mu + exp(log_sigma)*eps
// R11: fp16 m16n8k16 (R10) with K=128 per pipeline stage (2 x k64 sub-tiles,
// identical smem sub-layout) and STAGES=2 -> half the per-stage bubbles.
// ---------------------------------------------------------------------------
#define NROWS 8192
#define KDIM  4096
#define ODIM  4096

#define TILE_M 256
#define TILE_N 128
#define K_STAGE 128                        // k per pipeline stage
#define STAGES 2
#define K_ITERS (KDIM / K_STAGE)           // 32

#define A_HALF 32768                       // 256 rows x 64 halfs x 2B
#define B_HALF 16384                       // 128 rows x 64 halfs x 2B
#define A_BYTES (2 * A_HALF)               // 65536
#define B_BYTES (2 * B_HALF)               // 32768
#define STAGE_BYTES (A_BYTES + B_BYTES)    // 98304
#define OFF_BAR   (STAGES * STAGE_BYTES)   // 196608
#define SMEM_TOTAL (OFF_BAR + 64)

__device__ __half g_X[(size_t)NROWS * KDIM];
__device__ __half g_W[(size_t)ODIM * KDIM];
__device__ float  g_B[ODIM];

// ---------------------------------------------------------------------------
__device__ __forceinline__ uint32_t smem_u32(const void* p) {
    uint32_t a;
    asm("{ .reg .u64 t; cvta.to.shared.u64 t, %1; cvt.u32.u64 %0, t; }"
        : "=r"(a) : "l"(p));
    return a;
}
__device__ __forceinline__ void cp16(uint32_t smem_dst, const void* gptr) {
    asm volatile("cp.async.cg.shared.global [%0], [%1], 16;"
                 :: "r"(smem_dst), "l"(gptr) : "memory");
}
__device__ __forceinline__ void cp_async_arrive(uint32_t mbar) {
    asm volatile("cp.async.mbarrier.arrive.noinc.shared.b64 [%0];"
                 :: "r"(mbar) : "memory");
}
#define MBARRIER_INIT(addr, cnt) \
    asm volatile("mbarrier.init.shared.b64 [%0], %1;" :: "r"(addr), "r"(cnt) : "memory")
#define MBARRIER_ARRIVE(addr) \
    asm volatile("mbarrier.arrive.shared.b64 _, [%0];" :: "r"(addr) : "memory")

__device__ __forceinline__ void mbar_wait(uint32_t mbar, uint32_t parity) {
    uint32_t done;
    asm volatile(
        "{ .reg .pred p; mbarrier.try_wait.parity.acquire.cta.shared::cta.b64 p, [%1], %2;"
        " selp.b32 %0, 1, 0, p; }"
        : "=r"(done) : "r"(mbar), "r"(parity) : "memory");
    if (!done) {
        asm volatile(
            "{ .reg .pred P1;\n"
            "WAIT_LOOP_%=:\n"
            " mbarrier.try_wait.parity.acquire.cta.shared::cta.b64 P1, [%0], %1, 0x989680;\n"
            " @P1 bra.uni WAIT_DONE_%=;\n"
            " bra.uni WAIT_LOOP_%=;\n"
            "WAIT_DONE_%=:\n}"
            :: "r"(mbar), "r"(parity) : "memory");
    }
}

__device__ __forceinline__ void ldsm_x4(uint32_t* r, uint32_t addr) {
    asm volatile("ldmatrix.sync.aligned.m8n8.x4.shared.b16 {%0,%1,%2,%3}, [%4];"
                 : "=r"(r[0]), "=r"(r[1]), "=r"(r[2]), "=r"(r[3]) : "r"(addr));
}
__device__ __forceinline__ void mma_f16(float* c, const uint32_t* a,
                                        uint32_t b0, uint32_t b1) {
    asm volatile(
        "mma.sync.aligned.m16n8k16.row.col.f32.f16.f16.f32 "
        "{%0,%1,%2,%3}, {%4,%5,%6,%7}, {%8,%9}, {%0,%1,%2,%3};"
        : "+f"(c[0]), "+f"(c[1]), "+f"(c[2]), "+f"(c[3])
        : "r"(a[0]), "r"(a[1]), "r"(a[2]), "r"(a[3]), "r"(b0), "r"(b1));
}

// ---------------------------------------------------------------------------
// Prep kernels
// ---------------------------------------------------------------------------
__global__ void prep_x_kernel(const float4* __restrict__ x) {
    size_t i = (size_t)blockIdx.x * blockDim.x + threadIdx.x;
    float4 v0 = x[2 * i], v1 = x[2 * i + 1];
    __half2 h[4];
    h[0] = __floats2half2_rn(v0.x, v0.y);
    h[1] = __floats2half2_rn(v0.z, v0.w);
    h[2] = __floats2half2_rn(v1.x, v1.y);
    h[3] = __floats2half2_rn(v1.z, v1.w);
    reinterpret_cast<uint4*>(g_X)[i] = *reinterpret_cast<uint4*>(h);
}
__global__ void prep_w_kernel(const float4* __restrict__ mu,
                              const float4* __restrict__ ls,
                              const float4* __restrict__ eps) {
    size_t i = (size_t)blockIdx.x * blockDim.x + threadIdx.x;
    __half2 h[4];
    #pragma unroll
    for (int q = 0; q < 2; ++q) {
        float4 m = mu[2 * i + q], l = ls[2 * i + q], e = eps[2 * i + q];
        float4 w;
        w.x = m.x + expf(l.x) * e.x;
        w.y = m.y + expf(l.y) * e.y;
        w.z = m.z + expf(l.z) * e.z;
        w.w = m.w + expf(l.w) * e.w;
        h[2 * q + 0] = __floats2half2_rn(w.x, w.y);
        h[2 * q + 1] = __floats2half2_rn(w.z, w.w);
    }
    reinterpret_cast<uint4*>(g_W)[i] = *reinterpret_cast<uint4*>(h);
}
__global__ void prep_bias_kernel(const float* __restrict__ mub,
                                 const float* __restrict__ lsb,
                                 const float* __restrict__ epsb) {
    int i = blockIdx.x * blockDim.x + threadIdx.x;
    if (i < ODIM) g_B[i] = mub[i] + expf(lsb[i]) * epsb[i];
}

// ---------------------------------------------------------------------------
// GEMM: 1024 CTAs (32 m x 32 n, n fastest), 320 threads:
// warps 0-7 consumers (64x64 in 4x2), warps 8-9 producers (A/B halves).
// Stage layout: [A k-half0 32KB][A k-half1 32KB][B k-half0 16KB][B k-half1 16KB]
// ---------------------------------------------------------------------------
__global__ void __launch_bounds__(320, 1)
rand_linear_gemm_kernel(float* __restrict__ out) {
    extern __shared__ char smem[];
    const uint32_t sb = smem_u32(smem);
    const int tid = threadIdx.x;
    const int lane = tid & 31;
    const int wid = tid >> 5;

    const int m_tile = blockIdx.x >> 5;    // 32
    const int n_tile = blockIdx.x & 31;    // 32 (fast-varying: W stays L2-hot)
    const int m0 = m_tile * TILE_M;
    const int n0 = n_tile * TILE_N;

    #define FULL_BAR(s)  (sb + OFF_BAR + (s) * 16)
    #define EMPTY_BAR(s) (sb + OFF_BAR + (s) * 16 + 8)

    if (tid == 0) {
        #pragma unroll
        for (int s = 0; s < STAGES; ++s) {
            MBARRIER_INIT(FULL_BAR(s), 64u);    // 2 producer warps x 32 lanes
            MBARRIER_INIT(EMPTY_BAR(s), 256u);  // 8 consumer warps x 32 lanes
        }
    }
    __syncthreads();

    if (wid >= 8) {
        // ------- producer warps: ph halves of A-rows and B-rows, both k-halves
        const int ph = wid - 8;            // 0 or 1
        const int r0 = lane >> 3;          // 0..3
        const int tc = lane & 7;           // 16B chunk (8 halfs) in 128B row
        const __half* gA = g_X + (size_t)(m0 + ph * 128 + r0) * KDIM + tc * 8;
        const __half* gB = g_W + (size_t)(n0 + ph * 64 + r0) * KDIM + tc * 8;
        const uint32_t aOff = (uint32_t)(ph * 128) * 128u;  // row offset in half
        const uint32_t bOff = (uint32_t)(ph * 64) * 128u;
        const uint32_t sw0 = (uint32_t)r0 * 128u + (uint32_t)((tc ^ (r0 & 7)) << 4);
        const uint32_t sw1 = (uint32_t)(r0 + 4) * 128u +
                             (uint32_t)((tc ^ ((r0 + 4) & 7)) << 4);

        int slot = 0, phase = 1;
        for (int it = 0; it < K_ITERS; ++it) {
            mbar_wait(EMPTY_BAR(slot), phase);
            const uint32_t stg = sb + slot * STAGE_BYTES;
            #pragma unroll
            for (int hh = 0; hh < 2; ++hh) {
                const uint32_t aS = stg + hh * A_HALF + aOff;
                const uint32_t bS = stg + A_BYTES + hh * B_HALF + bOff;
                const __half* ga = gA + it * K_STAGE + hh * 64;
                const __half* gb = gB + it * K_STAGE + hh * 64;
                #pragma unroll
                for (int j = 0; j < 16; ++j) {   // A: 128 rows this warp
                    cp16(aS + sw0 + j * 1024u, ga + (size_t)(8 * j) * KDIM);
                    cp16(aS + sw1 + j * 1024u, ga + (size_t)(8 * j + 4) * KDIM);
                }
                #pragma unroll
                for (int j = 0; j < 8; ++j) {    // B: 64 rows this warp
                    cp16(bS + sw0 + j * 1024u, gb + (size_t)(8 * j) * KDIM);
                    cp16(bS + sw1 + j * 1024u, gb + (size_t)(8 * j + 4) * KDIM);
                }
            }
            cp_async_arrive(FULL_BAR(slot));
            if (++slot == STAGES) { slot = 0; phase ^= 1; }
        }
        return;
    }

    // --------------------------- consumer warps ---------------------------
    const int wm0 = (wid & 3) * 64;
    const int wn0 = (wid >> 2) * 64;

    const int la15 = lane & 15;
    const uint32_t hi = (uint32_t)(lane >> 4);
    uint32_t aRow[4], aX7[4], bRow[4], bX7[4];
    #pragma unroll
    for (int i = 0; i < 4; ++i) {
        const uint32_t ra = (uint32_t)(wm0 + i * 16 + la15);
        aRow[i] = ra * 128u; aX7[i] = ra & 7u;
        const uint32_t rb = (uint32_t)(wn0 + i * 16 + la15);
        bRow[i] = rb * 128u; bX7[i] = rb & 7u;
    }

    float acc[4][8][4];
    #pragma unroll
    for (int i = 0; i < 4; ++i)
        #pragma unroll
        for (int j = 0; j < 8; ++j)
            #pragma unroll
            for (int r = 0; r < 4; ++r) acc[i][j][r] = 0.f;

    uint32_t a[2][4][4], b[2][4][4];

    // kkl = k16 step within a k64 sub-tile (0..3); aB_/bB_ select sub-tile.
    #define LOAD_FRAGS(kkl, buf, aB_, bB_)                                    \
        do {                                                                  \
            const uint32_t kc2 = (uint32_t)((kkl) * 2) + hi;                  \
            _Pragma("unroll")                                                 \
            for (int i_ = 0; i_ < 4; ++i_)                                    \
                ldsm_x4(a[buf][i_], (aB_) + aRow[i_] + ((kc2 ^ aX7[i_]) << 4)); \
            _Pragma("unroll")                                                 \
            for (int j_ = 0; j_ < 4; ++j_)                                    \
                ldsm_x4(b[buf][j_], (bB_) + bRow[j_] + ((kc2 ^ bX7[j_]) << 4)); \
        } while (0)

    #define MMA_BLOCK(buf)                                                    \
        do {                                                                  \
            _Pragma("unroll")                                                 \
            for (int i_ = 0; i_ < 4; ++i_) {                                  \
                _Pragma("unroll")                                             \
                for (int j_ = 0; j_ < 4; ++j_) {                              \
                    mma_f16(acc[i_][2 * j_ + 0], a[buf][i_], b[buf][j_][0],   \
                            b[buf][j_][2]);                                   \
                    mma_f16(acc[i_][2 * j_ + 1], a[buf][i_], b[buf][j_][1],   \
                            b[buf][j_][3]);                                   \
                }                                                             \
            }                                                                 \
        } while (0)

    int slot = 0, phase = 0;
    for (int it = 0; it < K_ITERS; ++it) {
        mbar_wait(FULL_BAR(slot), phase);
        const uint32_t stg = sb + slot * STAGE_BYTES;
        const uint32_t a0 = stg;                    // A k-half 0
        const uint32_t a1 = stg + A_HALF;           // A k-half 1
        const uint32_t b0 = stg + A_BYTES;          // B k-half 0
        const uint32_t b1 = stg + A_BYTES + B_HALF; // B k-half 1

        // 8 k16 steps per stage, frag double-buffered
        LOAD_FRAGS(0, 0, a0, b0);
        LOAD_FRAGS(1, 1, a0, b0);
        MMA_BLOCK(0);                       // k 0-15
        LOAD_FRAGS(2, 0, a0, b0);
        MMA_BLOCK(1);                       // k 16-31
        LOAD_FRAGS(3, 1, a0, b0);
        MMA_BLOCK(0);                       // k 32-47
        LOAD_FRAGS(0, 0, a1, b1);
        MMA_BLOCK(1);                       // k 48-63
        LOAD_FRAGS(1, 1, a1, b1);
        MMA_BLOCK(0);                       // k 64-79
        LOAD_FRAGS(2, 0, a1, b1);
        MMA_BLOCK(1);                       // k 80-95
        LOAD_FRAGS(3, 1, a1, b1);
        MBARRIER_ARRIVE(EMPTY_BAR(slot));   // all stage reads issued
        MMA_BLOCK(0);                       // k 96-111
        MMA_BLOCK(1);                       // k 112-127

        if (++slot == STAGES) { slot = 0; phase ^= 1; }
    }

    // ---- epilogue: fused bias ----
    const int gid = lane >> 2;
    const int kc = lane & 3;
    #pragma unroll
    for (int j = 0; j < 8; ++j) {
        const int col = n0 + wn0 + j * 8 + kc * 2;
        float2 bv;
        bv.x = __ldg(&g_B[col]);
        bv.y = __ldg(&g_B[col + 1]);
        #pragma unroll
        for (int i = 0; i < 4; ++i) {
            const int row = m0 + wm0 + i * 16 + gid;
            float2 v0 = make_float2(acc[i][j][0] + bv.x, acc[i][j][1] + bv.y);
            float2 v1 = make_float2(acc[i][j][2] + bv.x, acc[i][j][3] + bv.y);
            *reinterpret_cast<float2*>(out + (size_t)row * ODIM + col) = v0;
            *reinterpret_cast<float2*>(out + (size_t)(row + 8) * ODIM + col) = v1;
        }
    }
}

// ---------------------------------------------------------------------------
extern "C" void kernel_launch(void* const* d_in, const int* in_sizes, int n_in,
                              void* d_out, int out_size) {
    const float* x    = (const float*)d_in[0];
    const float* muw  = (const float*)d_in[1];
    const float* lsw  = (const float*)d_in[2];
    const float* mub  = (const float*)d_in[3];
    const float* lsb  = (const float*)d_in[4];
    const float* epsw = (const float*)d_in[5];
    const float* epsb = (const float*)d_in[6];
    float* out = (float*)d_out;

    cudaFuncSetAttribute(rand_linear_gemm_kernel,
                         cudaFuncAttributeMaxDynamicSharedMemorySize, SMEM_TOTAL);

    prep_x_kernel<<<16384, 256>>>((const float4*)x);
    prep_w_kernel<<<8192, 256>>>((const float4*)muw, (const float4*)lsw,
                                 (const float4*)epsw);
    prep_bias_kernel<<<16, 256>>>(mub, lsb, epsb);

    rand_linear_gemm_kernel<<<(NROWS / TILE_M) * (ODIM / TILE_N), 320,
                              SMEM_TOTAL>>>(out);
}

// round 12
// speedup vs baseline: 1.1795x; 1.1795x over previous
#include <cuda_runtime.h>
#include <cuda_fp16.h>
#include <cstdint>
#include <cstddef>

// ---------------------------------------------------------------------------
// out[8192,4096] = x[8192,4096] @ W^T + b,  W = mu + exp(log_sigma)*eps
// R12 = R10 (best: fp16 m16n8k16, 256x128 CTA, K=64/stage) + STAGES=4 +
// fused single prep kernel. GEMM loop body byte-identical to R10.
// ---------------------------------------------------------------------------
#define NROWS 8192
#define KDIM  4096
#define ODIM  4096

#define TILE_M 256
#define TILE_N 128
#define TILE_K 64                          // fp16: 64 halfs = 128 B/row
#define STAGES 4
#define K_ITERS (KDIM / TILE_K)            // 64

#define A_BYTES (TILE_M * TILE_K * 2)      // 32768
#define B_BYTES (TILE_N * TILE_K * 2)      // 16384
#define STAGE_BYTES (A_BYTES + B_BYTES)    // 49152
#define OFF_BAR   (STAGES * STAGE_BYTES)   // 196608
#define SMEM_TOTAL (OFF_BAR + 128)

__device__ __half g_X[(size_t)NROWS * KDIM];
__device__ __half g_W[(size_t)ODIM * KDIM];
__device__ float  g_B[ODIM];

// ---------------------------------------------------------------------------
__device__ __forceinline__ uint32_t smem_u32(const void* p) {
    uint32_t a;
    asm("{ .reg .u64 t; cvta.to.shared.u64 t, %1; cvt.u32.u64 %0, t; }"
        : "=r"(a) : "l"(p));
    return a;
}
__device__ __forceinline__ void cp16(uint32_t smem_dst, const void* gptr) {
    asm volatile("cp.async.cg.shared.global [%0], [%1], 16;"
                 :: "r"(smem_dst), "l"(gptr) : "memory");
}
__device__ __forceinline__ void cp_async_arrive(uint32_t mbar) {
    asm volatile("cp.async.mbarrier.arrive.noinc.shared.b64 [%0];"
                 :: "r"(mbar) : "memory");
}
#define MBARRIER_INIT(addr, cnt) \
    asm volatile("mbarrier.init.shared.b64 [%0], %1;" :: "r"(addr), "r"(cnt) : "memory")
#define MBARRIER_ARRIVE(addr) \
    asm volatile("mbarrier.arrive.shared.b64 _, [%0];" :: "r"(addr) : "memory")

__device__ __forceinline__ void mbar_wait(uint32_t mbar, uint32_t parity) {
    uint32_t done;
    asm volatile(
        "{ .reg .pred p; mbarrier.try_wait.parity.acquire.cta.shared::cta.b64 p, [%1], %2;"
        " selp.b32 %0, 1, 0, p; }"
        : "=r"(done) : "r"(mbar), "r"(parity) : "memory");
    if (!done) {
        asm volatile(
            "{ .reg .pred P1;\n"
            "WAIT_LOOP_%=:\n"
            " mbarrier.try_wait.parity.acquire.cta.shared::cta.b64 P1, [%0], %1, 0x989680;\n"
            " @P1 bra.uni WAIT_DONE_%=;\n"
            " bra.uni WAIT_LOOP_%=;\n"
            "WAIT_DONE_%=:\n}"
            :: "r"(mbar), "r"(parity) : "memory");
    }
}

__device__ __forceinline__ void ldsm_x4(uint32_t* r, uint32_t addr) {
    asm volatile("ldmatrix.sync.aligned.m8n8.x4.shared.b16 {%0,%1,%2,%3}, [%4];"
                 : "=r"(r[0]), "=r"(r[1]), "=r"(r[2]), "=r"(r[3]) : "r"(addr));
}
__device__ __forceinline__ void mma_f16(float* c, const uint32_t* a,
                                        uint32_t b0, uint32_t b1) {
    asm volatile(
        "mma.sync.aligned.m16n8k16.row.col.f32.f16.f16.f32 "
        "{%0,%1,%2,%3}, {%4,%5,%6,%7}, {%8,%9}, {%0,%1,%2,%3};"
        : "+f"(c[0]), "+f"(c[1]), "+f"(c[2]), "+f"(c[3])
        : "r"(a[0]), "r"(a[1]), "r"(a[2]), "r"(a[3]), "r"(b0), "r"(b1));
}

// ---------------------------------------------------------------------------
// Fused prep: blocks [0, 16384) convert x; [16384, 24576) sample+convert W;
// block 24576 samples bias. One launch instead of three.
// ---------------------------------------------------------------------------
#define PREP_X_BLOCKS 16384
#define PREP_W_BLOCKS 8192
#define PREP_BLOCKS (PREP_X_BLOCKS + PREP_W_BLOCKS + 1)

__global__ void prep_all_kernel(const float4* __restrict__ x,
                                const float4* __restrict__ mu,
                                const float4* __restrict__ ls,
                                const float4* __restrict__ eps,
                                const float* __restrict__ mub,
                                const float* __restrict__ lsb,
                                const float* __restrict__ epsb) {
    const int b = blockIdx.x;
    if (b < PREP_X_BLOCKS) {
        size_t i = (size_t)b * blockDim.x + threadIdx.x;
        float4 v0 = x[2 * i], v1 = x[2 * i + 1];
        __half2 h[4];
        h[0] = __floats2half2_rn(v0.x, v0.y);
        h[1] = __floats2half2_rn(v0.z, v0.w);
        h[2] = __floats2half2_rn(v1.x, v1.y);
        h[3] = __floats2half2_rn(v1.z, v1.w);
        reinterpret_cast<uint4*>(g_X)[i] = *reinterpret_cast<uint4*>(h);
    } else if (b < PREP_X_BLOCKS + PREP_W_BLOCKS) {
        size_t i = (size_t)(b - PREP_X_BLOCKS) * blockDim.x + threadIdx.x;
        __half2 h[4];
        #pragma unroll
        for (int q = 0; q < 2; ++q) {
            float4 m = mu[2 * i + q], l = ls[2 * i + q], e = eps[2 * i + q];
            float4 w;
            w.x = m.x + expf(l.x) * e.x;
            w.y = m.y + expf(l.y) * e.y;
            w.z = m.z + expf(l.z) * e.z;
            w.w = m.w + expf(l.w) * e.w;
            h[2 * q + 0] = __floats2half2_rn(w.x, w.y);
            h[2 * q + 1] = __floats2half2_rn(w.z, w.w);
        }
        reinterpret_cast<uint4*>(g_W)[i] = *reinterpret_cast<uint4*>(h);
    } else {
        for (int i = threadIdx.x; i < ODIM; i += blockDim.x)
            g_B[i] = mub[i] + expf(lsb[i]) * epsb[i];
    }
}

// ---------------------------------------------------------------------------
// GEMM: 1024 CTAs (32 m x 32 n, n fastest), 320 threads:
// warps 0-7 consumers (64x64 in 4x2), warps 8-9 producers (A/B halves).
// (Loop body identical to R10 best; only STAGES differs.)
// ---------------------------------------------------------------------------
__global__ void __launch_bounds__(320, 1)
rand_linear_gemm_kernel(float* __restrict__ out) {
    extern __shared__ char smem[];
    const uint32_t sb = smem_u32(smem);
    const int tid = threadIdx.x;
    const int lane = tid & 31;
    const int wid = tid >> 5;

    const int m_tile = blockIdx.x >> 5;    // 32
    const int n_tile = blockIdx.x & 31;    // 32 (fast-varying: W stays L2-hot)
    const int m0 = m_tile * TILE_M;
    const int n0 = n_tile * TILE_N;

    #define FULL_BAR(s)  (sb + OFF_BAR + (s) * 16)
    #define EMPTY_BAR(s) (sb + OFF_BAR + (s) * 16 + 8)

    if (tid == 0) {
        #pragma unroll
        for (int s = 0; s < STAGES; ++s) {
            MBARRIER_INIT(FULL_BAR(s), 64u);    // 2 producer warps x 32 lanes
            MBARRIER_INIT(EMPTY_BAR(s), 256u);  // 8 consumer warps x 32 lanes
        }
    }
    __syncthreads();

    if (wid >= 8) {
        const int ph = wid - 8;            // 0 or 1
        const int r0 = lane >> 3;          // 0..3
        const int tc = lane & 7;           // 16B chunk (8 halfs) in 128B row
        const __half* gA = g_X + (size_t)(m0 + ph * 128 + r0) * KDIM + tc * 8;
        const __half* gB = g_W + (size_t)(n0 + ph * 64 + r0) * KDIM + tc * 8;
        const uint32_t aOff = (uint32_t)(ph * 128) * 128u;
        const uint32_t bOff = (uint32_t)(ph * 64) * 128u;
        const uint32_t sw0 = (uint32_t)r0 * 128u + (uint32_t)((tc ^ (r0 & 7)) << 4);
        const uint32_t sw1 = (uint32_t)(r0 + 4) * 128u +
                             (uint32_t)((tc ^ ((r0 + 4) & 7)) << 4);

        int slot = 0, phase = 1;
        for (int it = 0; it < K_ITERS; ++it) {
            mbar_wait(EMPTY_BAR(slot), phase);
            const uint32_t aS = sb + slot * STAGE_BYTES + aOff;
            const uint32_t bS = sb + slot * STAGE_BYTES + A_BYTES + bOff;
            const __half* ga = gA + it * TILE_K;
            const __half* gb = gB + it * TILE_K;
            #pragma unroll
            for (int j = 0; j < 16; ++j) {   // A half: 128 rows
                cp16(aS + sw0 + j * 1024u, ga + (size_t)(8 * j) * KDIM);
                cp16(aS + sw1 + j * 1024u, ga + (size_t)(8 * j + 4) * KDIM);
            }
            #pragma unroll
            for (int j = 0; j < 8; ++j) {    // B half: 64 rows
                cp16(bS + sw0 + j * 1024u, gb + (size_t)(8 * j) * KDIM);
                cp16(bS + sw1 + j * 1024u, gb + (size_t)(8 * j + 4) * KDIM);
            }
            cp_async_arrive(FULL_BAR(slot));
            if (++slot == STAGES) { slot = 0; phase ^= 1; }
        }
        return;
    }

    // --------------------------- consumer warps ---------------------------
    const int wm0 = (wid & 3) * 64;
    const int wn0 = (wid >> 2) * 64;

    const int la15 = lane & 15;
    const uint32_t hi = (uint32_t)(lane >> 4);
    uint32_t aRow[4], aX7[4], bRow[4], bX7[4];
    #pragma unroll
    for (int i = 0; i < 4; ++i) {
        const uint32_t ra = (uint32_t)(wm0 + i * 16 + la15);
        aRow[i] = ra * 128u; aX7[i] = ra & 7u;
        const uint32_t rb = (uint32_t)(wn0 + i * 16 + la15);
        bRow[i] = rb * 128u; bX7[i] = rb & 7u;
    }

    float acc[4][8][4];
    #pragma unroll
    for (int i = 0; i < 4; ++i)
        #pragma unroll
        for (int j = 0; j < 8; ++j)
            #pragma unroll
            for (int r = 0; r < 4; ++r) acc[i][j][r] = 0.f;

    uint32_t a[2][4][4], b[2][4][4];

    #define LOAD_FRAGS(kk, buf, aB_, bB_)                                     \
        do {                                                                  \
            const uint32_t kc2 = (uint32_t)((kk) * 2) + hi;                   \
            _Pragma("unroll")                                                 \
            for (int i_ = 0; i_ < 4; ++i_)                                    \
                ldsm_x4(a[buf][i_], (aB_) + aRow[i_] + ((kc2 ^ aX7[i_]) << 4)); \
            _Pragma("unroll")                                                 \
            for (int j_ = 0; j_ < 4; ++j_)                                    \
                ldsm_x4(b[buf][j_], (bB_) + bRow[j_] + ((kc2 ^ bX7[j_]) << 4)); \
        } while (0)

    #define MMA_BLOCK(buf)                                                    \
        do {                                                                  \
            _Pragma("unroll")                                                 \
            for (int i_ = 0; i_ < 4; ++i_) {                                  \
                _Pragma("unroll")                                             \
                for (int j_ = 0; j_ < 4; ++j_) {                              \
                    mma_f16(acc[i_][2 * j_ + 0], a[buf][i_], b[buf][j_][0],   \
                            b[buf][j_][2]);                                   \
                    mma_f16(acc[i_][2 * j_ + 1], a[buf][i_], b[buf][j_][1],   \
                            b[buf][j_][3]);                                   \
                }                                                             \
            }                                                                 \
        } while (0)

    int slot = 0, phase = 0;
    for (int it = 0; it < K_ITERS; ++it) {
        mbar_wait(FULL_BAR(slot), phase);
        const uint32_t aB = sb + slot * STAGE_BYTES;
        const uint32_t bB = aB + A_BYTES;

        LOAD_FRAGS(0, 0, aB, bB);
        LOAD_FRAGS(1, 1, aB, bB);
        MMA_BLOCK(0);                      // k 0-15
        LOAD_FRAGS(2, 0, aB, bB);
        MMA_BLOCK(1);                      // k 16-31
        LOAD_FRAGS(3, 1, aB, bB);
        MBARRIER_ARRIVE(EMPTY_BAR(slot));  // stage reads done — release early
        MMA_BLOCK(0);                      // k 32-47
        MMA_BLOCK(1);                      // k 48-63

        if (++slot == STAGES) { slot = 0; phase ^= 1; }
    }

    // ---- epilogue: fused bias ----
    const int gid = lane >> 2;
    const int kc = lane & 3;
    #pragma unroll
    for (int j = 0; j < 8; ++j) {
        const int col = n0 + wn0 + j * 8 + kc * 2;
        float2 bv;
        bv.x = __ldg(&g_B[col]);
        bv.y = __ldg(&g_B[col + 1]);
        #pragma unroll
        for (int i = 0; i < 4; ++i) {
            const int row = m0 + wm0 + i * 16 + gid;
            float2 v0 = make_float2(acc[i][j][0] + bv.x, acc[i][j][1] + bv.y);
            float2 v1 = make_float2(acc[i][j][2] + bv.x, acc[i][j][3] + bv.y);
            *reinterpret_cast<float2*>(out + (size_t)row * ODIM + col) = v0;
            *reinterpret_cast<float2*>(out + (size_t)(row + 8) * ODIM + col) = v1;
        }
    }
}

// ---------------------------------------------------------------------------
extern "C" void kernel_launch(void* const* d_in, const int* in_sizes, int n_in,
                              void* d_out, int out_size) {
    const float* x    = (const float*)d_in[0];
    const float* muw  = (const float*)d_in[1];
    const float* lsw  = (const float*)d_in[2];
    const float* mub  = (const float*)d_in[3];
    const float* lsb  = (const float*)d_in[4];
    const float* epsw = (const float*)d_in[5];
    const float* epsb = (const float*)d_in[6];
    float* out = (float*)d_out;

    cudaFuncSetAttribute(rand_linear_gemm_kernel,
                         cudaFuncAttributeMaxDynamicSharedMemorySize, SMEM_TOTAL);

    prep_all_kernel<<<PREP_BLOCKS, 256>>>((const float4*)x, (const float4*)muw,
                                          (const float4*)lsw, (const float4*)epsw,
                                          mub, lsb, epsb);

    rand_linear_gemm_kernel<<<(NROWS / TILE_M) * (ODIM / TILE_N), 320,
                              SMEM_TOTAL>>>(out);
}